// round 8
// baseline (speedup 1.0000x reference)
#include <cuda_runtime.h>
#include <cuda_bf16.h>
#include <math.h>
#include <stdint.h>

// Problem constants
#define BB 4
#define LL 2048
#define DD 512
#define HH 8
#define DKK 64
#define UU 24
#define BH (BB*HH)
#define MTOT (BB*LL)     // 8192 rows per GEMM

// ---------------- scratch (device globals; no allocation allowed) ----------
__device__ float g_q[BB*HH*LL*DKK];     // (B,H,L,DK)
__device__ float g_k[BB*HH*LL*DKK];
__device__ float g_v[BB*HH*LL*DKK];
__device__ float g_m[BB*HH*LL];
__device__ int   g_top[BB*HH*UU];
__device__ float g_att[BB*HH*UU*DKK];
__device__ float g_ctx[BB*LL*DD];       // (b, l, h*DK+dk)

// pre-split transposed weights W^T[n][k] in bf16 hi/lo (Wq,Wk,Wv,Wo)
__device__ __nv_bfloat16 g_wh[4][DD*DD];
__device__ __nv_bfloat16 g_wl[4][DD*DD];

// cumsum scratch
__device__ float g_segsum[BH][16][4][DKK];
__device__ float g_chpre[BH][16][DKK];

// =========================== helpers =======================================
__device__ __forceinline__ uint32_t smem_u32(const void* p) {
    uint32_t a;
    asm("{ .reg .u64 t; cvta.to.shared.u64 t, %1; cvt.u32.u64 %0, t; }"
        : "=r"(a) : "l"(p));
    return a;
}
__device__ __forceinline__ void cpasync16(uint32_t saddr, const void* gptr) {
    asm volatile("cp.async.cg.shared.global [%0], [%1], 16;"
                 :: "r"(saddr), "l"(__cvta_generic_to_global(gptr)) : "memory");
}
__device__ __forceinline__ void cp_commit() {
    asm volatile("cp.async.commit_group;" ::: "memory");
}
template<int N>
__device__ __forceinline__ void cp_wait() {
    asm volatile("cp.async.wait_group %0;" :: "n"(N) : "memory");
}
__device__ __forceinline__ void mma_bf16(float& c0, float& c1, float& c2, float& c3,
                                         uint32_t a0, uint32_t a1, uint32_t a2, uint32_t a3,
                                         uint32_t b0, uint32_t b1) {
    asm volatile("mma.sync.aligned.m16n8k16.row.col.f32.bf16.bf16.f32 "
                 "{%0,%1,%2,%3}, {%4,%5,%6,%7}, {%8,%9}, {%0,%1,%2,%3};"
                 : "+f"(c0), "+f"(c1), "+f"(c2), "+f"(c3)
                 : "r"(a0), "r"(a1), "r"(a2), "r"(a3), "r"(b0), "r"(b1));
}
__device__ __forceinline__ void ldsm4(uint32_t& r0, uint32_t& r1, uint32_t& r2, uint32_t& r3,
                                      uint32_t addr) {
    asm volatile("ldmatrix.sync.aligned.m8n8.x4.shared.b16 {%0,%1,%2,%3}, [%4];"
                 : "=r"(r0), "=r"(r1), "=r"(r2), "=r"(r3) : "r"(addr));
}
__device__ __forceinline__ void split2(float x, __nv_bfloat16& h, __nv_bfloat16& l) {
    h = __float2bfloat16_rn(x);
    l = __float2bfloat16_rn(x - __bfloat162float(h));
}
__device__ __forceinline__ uint32_t pack2(__nv_bfloat16 a, __nv_bfloat16 b) {
    return (uint32_t)__bfloat16_as_ushort(a) | ((uint32_t)__bfloat16_as_ushort(b) << 16);
}

// W[k][n] -> W^T[n][k] bf16 hi/lo, tiled transpose. grid (16,16,4), block (32,8)
__global__ __launch_bounds__(256) void transpose_split_kernel(const float* __restrict__ Wq,
                                                              const float* __restrict__ Wk,
                                                              const float* __restrict__ Wv,
                                                              const float* __restrict__ Wo)
{
    __shared__ float tile[32][33];
    const int z = blockIdx.z;
    const float* W = (z == 0) ? Wq : (z == 1) ? Wk : (z == 2) ? Wv : Wo;
    const int k0 = blockIdx.y * 32, n0 = blockIdx.x * 32;
#pragma unroll
    for (int r = 0; r < 32; r += 8)
        tile[threadIdx.y + r][threadIdx.x] = W[(size_t)(k0 + threadIdx.y + r) * DD + n0 + threadIdx.x];
    __syncthreads();
#pragma unroll
    for (int r = 0; r < 32; r += 8) {
        const int n = n0 + threadIdx.y + r, k = k0 + threadIdx.x;
        __nv_bfloat16 h, l;
        split2(tile[threadIdx.x][threadIdx.y + r], h, l);
        g_wh[z][(size_t)n * DD + k] = h;
        g_wl[z][(size_t)n * DD + k] = l;
    }
}

// ============== HMMA GEMM: 128x64 tile, reg-split A, 3-stage ===============
#define STG 40                          // smem row stride, bf16 elems
#define A_ARR_B (128*STG*2)             // 10240 B
#define B_ARR_B (64*STG*2)              // 5120 B
#define OFF_AH 0
#define OFF_AL (A_ARR_B)                // 10240
#define OFF_BH (2*A_ARR_B)              // 20480
#define OFF_BL (2*A_ARR_B + B_ARR_B)    // 25600
#define STAGE_B (2*A_ARR_B + 2*B_ARR_B) // 30720
#define GSMEM (3*STAGE_B)               // 92160

// SCATTER=0: row-major dst[m][512]; SCATTER=1: (B,H,L,DK) layout
template<int SCATTER>
__device__ __forceinline__ void gemm_core(const float* __restrict__ A,
                                          const __nv_bfloat16* __restrict__ Bh,
                                          const __nv_bfloat16* __restrict__ Bl,
                                          const float* __restrict__ bias,
                                          float* __restrict__ dst, char* smraw)
{
    const int tid = threadIdx.x;
    const int m0 = blockIdx.y * 128, n0 = blockIdx.x * 64;
    const uint32_t sbase = smem_u32(smraw);

    const int wid = tid >> 5, lane = tid & 31;
    const int wm = (wid >> 1) * 32;       // 0,32,64,96
    const int wn = (wid & 1) * 32;        // 0,32
    const int g  = lane >> 2;             // 0..7
    const int q2 = (lane & 3) * 2;        // 0,2,4,6

    // ldmatrix per-lane address components (elements)
    const int aRow = wm + (lane & 7) + ((lane >> 3) & 1) * 8;   // + i*16
    const int aColE = (lane >> 4) * 8;                          // + ks
    const int bRow = wn + (lane & 7) + ((lane >> 4) & 1) * 8;   // + jp*16
    const int bColE = ((lane >> 3) & 1) * 8;                    // + ks

    // A-load / STS geometry: thread owns row=tid>>1, half=(tid&1)*16
    const int lrow = tid >> 1, lhalf = (tid & 1) * 16;
    const float* Arow = A + (size_t)(m0 + lrow) * DD + lhalf;
    // B cp.async: row=tid>>2, kp=(tid&3)*8  (64*32/8 = 256 = blockDim)
    const int brow = tid >> 2, bkp = (tid & 3) * 8;

    float acc[2][4][4];
#pragma unroll
    for (int i = 0; i < 2; i++)
#pragma unroll
        for (int j = 0; j < 4; j++)
#pragma unroll
            for (int r = 0; r < 4; r++) acc[i][j][r] = 0.f;

    float4 areg[2][4];

    // preload chunk 0
#pragma unroll
    for (int qq = 0; qq < 4; qq++) areg[0][qq] = *(const float4*)(Arow + qq * 4);
    {
        const uint32_t s = sbase;  // stage 0
        cpasync16(s + OFF_BH + (uint32_t)(brow * STG + bkp) * 2,
                  Bh + (size_t)(n0 + brow) * DD + bkp);
        cpasync16(s + OFF_BL + (uint32_t)(brow * STG + bkp) * 2,
                  Bl + (size_t)(n0 + brow) * DD + bkp);
        cp_commit();
    }

    for (int c = 0; c < 16; c++) {
        const int st = (c == 0) ? 0 : (c % 3);
        const uint32_t stb = sbase + (uint32_t)(c % 3) * STAGE_B;
        (void)st;

        // STS: split regs (chunk c) -> Ah/Al in stage c%3
        {
            __nv_bfloat16* ah = (__nv_bfloat16*)(smraw + (c % 3) * STAGE_B + OFF_AH);
            __nv_bfloat16* al = (__nv_bfloat16*)(smraw + (c % 3) * STAGE_B + OFF_AL);
#pragma unroll
            for (int qq = 0; qq < 4; qq++) {
                float4 v = areg[c & 1][qq];
                __nv_bfloat16 h0, h1, h2, h3, l0, l1, l2, l3;
                split2(v.x, h0, l0); split2(v.y, h1, l1);
                split2(v.z, h2, l2); split2(v.w, h3, l3);
                uint2 uh = { pack2(h0, h1), pack2(h2, h3) };
                uint2 ul = { pack2(l0, l1), pack2(l2, l3) };
                *(uint2*)(ah + lrow * STG + lhalf + qq * 4) = uh;
                *(uint2*)(al + lrow * STG + lhalf + qq * 4) = ul;
            }
        }

        // prefetch chunk c+1: A into regs, B into stage (c+1)%3
        if (c < 15) {
            const int k1 = (c + 1) * 32;
#pragma unroll
            for (int qq = 0; qq < 4; qq++)
                areg[(c + 1) & 1][qq] = *(const float4*)(Arow + k1 + qq * 4);
            const uint32_t s = sbase + (uint32_t)((c + 1) % 3) * STAGE_B;
            cpasync16(s + OFF_BH + (uint32_t)(brow * STG + bkp) * 2,
                      Bh + (size_t)(n0 + brow) * DD + k1 + bkp);
            cpasync16(s + OFF_BL + (uint32_t)(brow * STG + bkp) * 2,
                      Bl + (size_t)(n0 + brow) * DD + k1 + bkp);
            cp_commit();
            cp_wait<1>();
        } else {
            cp_wait<0>();
        }
        __syncthreads();

        const uint32_t aH = stb + OFF_AH + (uint32_t)(aRow * STG + aColE) * 2;
        const uint32_t aL = stb + OFF_AL + (uint32_t)(aRow * STG + aColE) * 2;
        const uint32_t bH = stb + OFF_BH + (uint32_t)(bRow * STG + bColE) * 2;
        const uint32_t bL = stb + OFF_BL + (uint32_t)(bRow * STG + bColE) * 2;

#pragma unroll
        for (int ks = 0; ks < 32; ks += 16) {
            uint32_t ah4[2][4], al4[2][4], bh4[2][4], bl4[2][4];
#pragma unroll
            for (int i = 0; i < 2; i++)
                ldsm4(ah4[i][0], ah4[i][1], ah4[i][2], ah4[i][3],
                      aH + (uint32_t)(i * 16 * STG + ks) * 2);
#pragma unroll
            for (int jp = 0; jp < 2; jp++)
                ldsm4(bh4[jp][0], bh4[jp][1], bh4[jp][2], bh4[jp][3],
                      bH + (uint32_t)(jp * 16 * STG + ks) * 2);
#pragma unroll
            for (int jp = 0; jp < 2; jp++)
                ldsm4(bl4[jp][0], bl4[jp][1], bl4[jp][2], bl4[jp][3],
                      bL + (uint32_t)(jp * 16 * STG + ks) * 2);
#pragma unroll
            for (int i = 0; i < 2; i++)
                ldsm4(al4[i][0], al4[i][1], al4[i][2], al4[i][3],
                      aL + (uint32_t)(i * 16 * STG + ks) * 2);

#pragma unroll
            for (int i = 0; i < 2; i++)
#pragma unroll
                for (int j = 0; j < 4; j++) {
                    const int jp = j >> 1, jo = (j & 1) * 2;
                    mma_bf16(acc[i][j][0], acc[i][j][1], acc[i][j][2], acc[i][j][3],
                             ah4[i][0], ah4[i][1], ah4[i][2], ah4[i][3],
                             bh4[jp][jo], bh4[jp][jo + 1]);
                }
#pragma unroll
            for (int i = 0; i < 2; i++)
#pragma unroll
                for (int j = 0; j < 4; j++) {
                    const int jp = j >> 1, jo = (j & 1) * 2;
                    mma_bf16(acc[i][j][0], acc[i][j][1], acc[i][j][2], acc[i][j][3],
                             ah4[i][0], ah4[i][1], ah4[i][2], ah4[i][3],
                             bl4[jp][jo], bl4[jp][jo + 1]);
                }
#pragma unroll
            for (int i = 0; i < 2; i++)
#pragma unroll
                for (int j = 0; j < 4; j++) {
                    const int jp = j >> 1, jo = (j & 1) * 2;
                    mma_bf16(acc[i][j][0], acc[i][j][1], acc[i][j][2], acc[i][j][3],
                             al4[i][0], al4[i][1], al4[i][2], al4[i][3],
                             bh4[jp][jo], bh4[jp][jo + 1]);
                }
        }
    }

    // epilogue
#pragma unroll
    for (int i = 0; i < 2; i++) {
#pragma unroll
        for (int j = 0; j < 4; j++) {
            const int gm0 = m0 + wm + i * 16 + g;
            const int gn  = n0 + wn + j * 8 + q2;
            const float b0 = bias[gn], b1 = bias[gn + 1];
            const float v0 = acc[i][j][0] + b0, v1 = acc[i][j][1] + b1;
            const float v2 = acc[i][j][2] + b0, v3 = acc[i][j][3] + b1;
            if (SCATTER == 0) {
                float* p0 = dst + (size_t)gm0 * DD + gn;
                p0[0] = v0; p0[1] = v1;
                float* p1 = dst + (size_t)(gm0 + 8) * DD + gn;
                p1[0] = v2; p1[1] = v3;
            } else {
                const int h = gn >> 6, dk = gn & 63;
                {
                    const int b = gm0 >> 11, l = gm0 & 2047;
                    float* p = dst + (((size_t)(b * HH + h)) * LL + l) * DKK + dk;
                    p[0] = v0; p[1] = v1;
                }
                {
                    const int gm1 = gm0 + 8;
                    const int b = gm1 >> 11, l = gm1 & 2047;
                    float* p = dst + (((size_t)(b * HH + h)) * LL + l) * DKK + dk;
                    p[0] = v2; p[1] = v3;
                }
            }
        }
    }
}

__global__ __launch_bounds__(256, 2) void hgemm_qkv(const float* __restrict__ q,
                                                    const float* __restrict__ k,
                                                    const float* __restrict__ v,
                                                    const float* __restrict__ bq,
                                                    const float* __restrict__ bk,
                                                    const float* __restrict__ bv)
{
    extern __shared__ char smraw[];
    const int z = blockIdx.z;
    const float* A = (z == 0) ? q : (z == 1) ? k : v;
    const float* bias = (z == 0) ? bq : (z == 1) ? bk : bv;
    float* dst = (z == 0) ? g_q : (z == 1) ? g_k : g_v;
    gemm_core<1>(A, g_wh[z], g_wl[z], bias, dst, smraw);
}

__global__ __launch_bounds__(256, 2) void hgemm_out(const float* __restrict__ bo,
                                                    float* __restrict__ outp)
{
    extern __shared__ char smraw[];
    gemm_core<0>((const float*)g_ctx, g_wh[3], g_wl[3], bo, outp, smraw);
}

// =========================== non-GEMM kernels ==============================
__global__ __launch_bounds__(256) void probe_kernel(const int* __restrict__ idx)
{
    const int w = (blockIdx.x * blockDim.x + threadIdx.x) >> 5;
    const int lane = threadIdx.x & 31;
    if (w >= BB * HH * LL) return;
    const int l = w & (LL - 1);
    const int bh = w >> 11;

    const float* qrow = g_q + (size_t)(bh * LL + l) * DKK;
    const float2 qv = *(const float2*)(qrow + lane * 2);
    const float* kbase = g_k + (size_t)bh * LL * DKK;
    const int* ip = idx + l * UU;
    const int myidx = (lane < UU) ? ip[lane] : 0;

    float mx = -INFINITY, sm = 0.f;
#pragma unroll 4
    for (int s = 0; s < UU; s++) {
        const int j = __shfl_sync(0xffffffffu, myidx, s);
        const float2 kk = *(const float2*)(kbase + (size_t)j * DKK + lane * 2);
        float p = qv.x * kk.x + qv.y * kk.y;
#pragma unroll
        for (int o = 16; o > 0; o >>= 1) p += __shfl_xor_sync(0xffffffffu, p, o);
        mx = fmaxf(mx, p);
        sm += p;
    }
    if (lane == 0) g_m[w] = mx - sm * (1.0f / LL);
}

__global__ __launch_bounds__(256) void topk_kernel()
{
    __shared__ float swv[8];
    __shared__ int   swi[8];
    __shared__ int   swin;
    const int bh = blockIdx.x;
    const int t = threadIdx.x;
    const int wid = t >> 5, lane = t & 31;

    float v[8];
#pragma unroll
    for (int j = 0; j < 8; j++) v[j] = g_m[(size_t)bh * LL + j * 256 + t];

    for (int iter = 0; iter < UU; iter++) {
        float bv = v[0]; int bj = 0;
#pragma unroll
        for (int j = 1; j < 8; j++) if (v[j] > bv) { bv = v[j]; bj = j; }
        int bi = bj * 256 + t;
#pragma unroll
        for (int o = 16; o > 0; o >>= 1) {
            const float ov = __shfl_xor_sync(0xffffffffu, bv, o);
            const int   oi = __shfl_xor_sync(0xffffffffu, bi, o);
            if (ov > bv || (ov == bv && oi < bi)) { bv = ov; bi = oi; }
        }
        if (lane == 0) { swv[wid] = bv; swi[wid] = bi; }
        __syncthreads();
        if (t == 0) {
            float mv = swv[0]; int mi = swi[0];
#pragma unroll
            for (int w = 1; w < 8; w++)
                if (swv[w] > mv || (swv[w] == mv && swi[w] < mi)) { mv = swv[w]; mi = swi[w]; }
            g_top[bh * UU + iter] = mi;
            swin = mi;
        }
        __syncthreads();
        const int win = swin;
        if ((win & 255) == t) v[win >> 8] = -INFINITY;
    }
}

#define QG 4
__global__ __launch_bounds__(256) void attn_kernel()
{
    __shared__ float qs[QG][DKK];
    __shared__ float sc[QG][LL];
    __shared__ float red[256];
    __shared__ int   pos_s[QG];

    const int bh = blockIdx.x / (UU / QG);
    const int grp = blockIdx.x % (UU / QG);
    const int t = threadIdx.x;
    const int wid = t >> 5, lane = t & 31;

    const float* kb = g_k + (size_t)bh * LL * DKK;
    const float* vb = g_v + (size_t)bh * LL * DKK;

    {
        const int u = t >> 6, d = t & 63;
        const int p = g_top[bh * UU + grp * QG + u];
        if (d == 0) pos_s[u] = p;
        qs[u][d] = g_q[((size_t)bh * LL + p) * DKK + d];
    }
    __syncthreads();

    const float scale = rsqrtf((float)DD);

    float lmax[QG];
#pragma unroll
    for (int u = 0; u < QG; u++) lmax[u] = -INFINITY;

    for (int j = t; j < LL; j += 256) {
        const float* kr = kb + (size_t)j * DKK;
        float dot[QG];
#pragma unroll
        for (int u = 0; u < QG; u++) dot[u] = 0.f;
#pragma unroll
        for (int d4 = 0; d4 < 16; d4++) {
            float4 kk = *(const float4*)(kr + d4 * 4);
#pragma unroll
            for (int u = 0; u < QG; u++) {
                dot[u] += qs[u][d4 * 4] * kk.x + qs[u][d4 * 4 + 1] * kk.y +
                          qs[u][d4 * 4 + 2] * kk.z + qs[u][d4 * 4 + 3] * kk.w;
            }
        }
#pragma unroll
        for (int u = 0; u < QG; u++) {
            const float s = (j > pos_s[u]) ? -INFINITY : dot[u] * scale;
            sc[u][j] = s;
            lmax[u] = fmaxf(lmax[u], s);
        }
    }
#pragma unroll
    for (int u = 0; u < QG; u++) {
        float m = lmax[u];
#pragma unroll
        for (int o = 16; o > 0; o >>= 1) m = fmaxf(m, __shfl_xor_sync(0xffffffffu, m, o));
        if (lane == 0) red[u * 8 + wid] = m;
    }
    __syncthreads();
    float mx[QG];
#pragma unroll
    for (int u = 0; u < QG; u++) {
        float m = -INFINITY;
#pragma unroll
        for (int w = 0; w < 8; w++) m = fmaxf(m, red[u * 8 + w]);
        mx[u] = m;
    }
    __syncthreads();

    float lsum[QG];
#pragma unroll
    for (int u = 0; u < QG; u++) lsum[u] = 0.f;
    for (int j = t; j < LL; j += 256) {
#pragma unroll
        for (int u = 0; u < QG; u++) {
            const float p = __expf(sc[u][j] - mx[u]);
            sc[u][j] = p;
            lsum[u] += p;
        }
    }
#pragma unroll
    for (int u = 0; u < QG; u++) {
        float s = lsum[u];
#pragma unroll
        for (int o = 16; o > 0; o >>= 1) s += __shfl_xor_sync(0xffffffffu, s, o);
        if (lane == 0) red[u * 8 + wid] = s;
    }
    __syncthreads();
    float inv[QG];
#pragma unroll
    for (int u = 0; u < QG; u++) {
        float s = 0.f;
#pragma unroll
        for (int w = 0; w < 8; w++) s += red[u * 8 + w];
        inv[u] = 1.0f / s;
    }
    __syncthreads();

    const int d = t & 63, g4 = t >> 6;
    float acc[QG];
#pragma unroll
    for (int u = 0; u < QG; u++) acc[u] = 0.f;
    const int j0 = g4 * (LL / 4), j1 = j0 + (LL / 4);
    for (int j = j0; j < j1; j++) {
        const float v = vb[(size_t)j * DKK + d];
#pragma unroll
        for (int u = 0; u < QG; u++) acc[u] += sc[u][j] * v;
    }
#pragma unroll
    for (int u = 0; u < QG; u++) {
        red[t] = acc[u];
        __syncthreads();
        if (t < DKK) {
            const float o = (red[t] + red[t + 64] + red[t + 128] + red[t + 192]) * inv[u];
            g_att[(size_t)(bh * UU + grp * QG + u) * DKK + t] = o;
        }
        __syncthreads();
    }
}

// ---- cumsum, 3-phase ------------------------------------------------------
__global__ __launch_bounds__(256) void cumsum_p1()
{
    const int bh = blockIdx.x, ch = blockIdx.y;
    const int t = threadIdx.x;
    const int d = t & 63, seg = t >> 6;
    const float* vb = g_v + (size_t)bh * LL * DKK;
    const int l0 = ch * 128 + seg * 32;
    float s = 0.f;
#pragma unroll 4
    for (int l = l0; l < l0 + 32; l++) s += vb[(size_t)l * DKK + d];
    g_segsum[bh][ch][seg][d] = s;
}
__global__ __launch_bounds__(64) void cumsum_p2()
{
    const int bh = blockIdx.x, d = threadIdx.x;
    float run = 0.f;
#pragma unroll
    for (int ch = 0; ch < 16; ch++) {
        g_chpre[bh][ch][d] = run;
        run += g_segsum[bh][ch][0][d] + g_segsum[bh][ch][1][d] +
               g_segsum[bh][ch][2][d] + g_segsum[bh][ch][3][d];
    }
}
__global__ __launch_bounds__(256) void cumsum_p3()
{
    const int bh = blockIdx.x, ch = blockIdx.y;
    const int b = bh >> 3, h = bh & 7;
    const int t = threadIdx.x;
    const int d = t & 63, seg = t >> 6;
    const float* vb = g_v + (size_t)bh * LL * DKK;

    float off = g_chpre[bh][ch][d];
    for (int s = 0; s < seg; s++) off += g_segsum[bh][ch][s][d];

    const int l0 = ch * 128 + seg * 32;
    float acc = off;
    float* cb = g_ctx + (size_t)b * LL * DD + h * DKK;
#pragma unroll 4
    for (int l = l0; l < l0 + 32; l++) {
        acc += vb[(size_t)l * DKK + d];
        cb[(size_t)l * DD + d] = acc;
    }
}

__global__ void scatter_kernel()
{
    const int i = blockIdx.x * blockDim.x + threadIdx.x;
    if (i >= BB * HH * UU * DKK) return;
    const int d = i & 63;
    const int r = i >> 6;
    const int bh = r / UU;
    const int b = bh >> 3, h = bh & 7;
    const int pos = g_top[r];
    g_ctx[((size_t)b * LL + pos) * DD + h * DKK + d] = g_att[i];
}

// ---------------------------------------------------------------------------
extern "C" void kernel_launch(void* const* d_in, const int* in_sizes, int n_in,
                              void* d_out, int out_size)
{
    const float* queries = (const float*)d_in[0];
    const float* keys    = (const float*)d_in[1];
    const float* values  = (const float*)d_in[2];
    const int*   index_sample = (const int*)d_in[3];
    const float* Wq = (const float*)d_in[4];
    const float* bq = (const float*)d_in[5];
    const float* Wk = (const float*)d_in[6];
    const float* bk = (const float*)d_in[7];
    const float* Wv = (const float*)d_in[8];
    const float* bv = (const float*)d_in[9];
    const float* Wo = (const float*)d_in[10];
    const float* bo = (const float*)d_in[11];
    float* out = (float*)d_out;

    cudaFuncSetAttribute(hgemm_qkv, cudaFuncAttributeMaxDynamicSharedMemorySize, GSMEM);
    cudaFuncSetAttribute(hgemm_out, cudaFuncAttributeMaxDynamicSharedMemorySize, GSMEM);

    transpose_split_kernel<<<dim3(16, 16, 4), dim3(32, 8)>>>(Wq, Wk, Wv, Wo);

    hgemm_qkv<<<dim3(DD / 64, MTOT / 128, 3), 256, GSMEM>>>(queries, keys, values, bq, bk, bv);

    probe_kernel<<<(BB * HH * LL * 32) / 256, 256>>>(index_sample);
    topk_kernel<<<BH, 256>>>();
    attn_kernel<<<BH * (UU / QG), 256>>>();
    cumsum_p1<<<dim3(BH, 16), 256>>>();
    cumsum_p2<<<BH, 64>>>();
    cumsum_p3<<<dim3(BH, 16), 256>>>();
    scatter_kernel<<<(BB * HH * UU * DKK + 255) / 256, 256>>>();

    hgemm_out<<<dim3(DD / 64, MTOT / 128, 1), 256, GSMEM>>>(bo, out);
}

// round 10
// speedup vs baseline: 1.1178x; 1.1178x over previous
#include <cuda_runtime.h>
#include <cuda_bf16.h>
#include <cuda_fp16.h>
#include <math.h>
#include <stdint.h>

// Problem constants
#define BB 4
#define LL 2048
#define DD 512
#define HH 8
#define DKK 64
#define UU 24
#define BH (BB*HH)
#define MTOT (BB*LL)     // 8192 rows per GEMM

// ---------------- scratch (device globals; no allocation allowed) ----------
__device__ float g_q[BB*HH*LL*DKK];     // (B,H,L,DK)
__device__ float g_k[BB*HH*LL*DKK];
__device__ float g_v[BB*HH*LL*DKK];
__device__ float g_m[BB*HH*LL];
__device__ int   g_top[BB*HH*UU];
__device__ float g_att[BB*HH*UU*DKK];
__device__ float g_ctx[BB*LL*DD];       // (b, l, h*DK+dk)

// pre-split transposed weights W^T[n][k]: bf16 hi/lo for Wq,Wk; fp16 for Wv,Wo
__device__ __nv_bfloat16 g_wh[2][DD*DD];
__device__ __nv_bfloat16 g_wl[2][DD*DD];
__device__ __half        g_wf[2][DD*DD];

// cumsum scratch
__device__ float g_segsum[BH][16][4][DKK];
__device__ float g_chpre[BH][16][DKK];

// =========================== helpers =======================================
__device__ __forceinline__ uint32_t smem_u32(const void* p) {
    uint32_t a;
    asm("{ .reg .u64 t; cvta.to.shared.u64 t, %1; cvt.u32.u64 %0, t; }"
        : "=r"(a) : "l"(p));
    return a;
}
__device__ __forceinline__ void cpasync16(uint32_t saddr, const void* gptr) {
    asm volatile("cp.async.cg.shared.global [%0], [%1], 16;"
                 :: "r"(saddr), "l"(__cvta_generic_to_global(gptr)) : "memory");
}
__device__ __forceinline__ void cp_commit() {
    asm volatile("cp.async.commit_group;" ::: "memory");
}
template<int N>
__device__ __forceinline__ void cp_wait() {
    asm volatile("cp.async.wait_group %0;" :: "n"(N) : "memory");
}
template<int F16>
__device__ __forceinline__ void mma_any(float& c0, float& c1, float& c2, float& c3,
                                        uint32_t a0, uint32_t a1, uint32_t a2, uint32_t a3,
                                        uint32_t b0, uint32_t b1) {
    if (F16)
        asm volatile("mma.sync.aligned.m16n8k16.row.col.f32.f16.f16.f32 "
                     "{%0,%1,%2,%3}, {%4,%5,%6,%7}, {%8,%9}, {%0,%1,%2,%3};"
                     : "+f"(c0), "+f"(c1), "+f"(c2), "+f"(c3)
                     : "r"(a0), "r"(a1), "r"(a2), "r"(a3), "r"(b0), "r"(b1));
    else
        asm volatile("mma.sync.aligned.m16n8k16.row.col.f32.bf16.bf16.f32 "
                     "{%0,%1,%2,%3}, {%4,%5,%6,%7}, {%8,%9}, {%0,%1,%2,%3};"
                     : "+f"(c0), "+f"(c1), "+f"(c2), "+f"(c3)
                     : "r"(a0), "r"(a1), "r"(a2), "r"(a3), "r"(b0), "r"(b1));
}
__device__ __forceinline__ void ldsm4(uint32_t& r0, uint32_t& r1, uint32_t& r2, uint32_t& r3,
                                      uint32_t addr) {
    asm volatile("ldmatrix.sync.aligned.m8n8.x4.shared.b16 {%0,%1,%2,%3}, [%4];"
                 : "=r"(r0), "=r"(r1), "=r"(r2), "=r"(r3) : "r"(addr));
}
__device__ __forceinline__ void split2(float x, __nv_bfloat16& h, __nv_bfloat16& l) {
    h = __float2bfloat16_rn(x);
    l = __float2bfloat16_rn(x - __bfloat162float(h));
}
__device__ __forceinline__ uint32_t pack2(__nv_bfloat16 a, __nv_bfloat16 b) {
    return (uint32_t)__bfloat16_as_ushort(a) | ((uint32_t)__bfloat16_as_ushort(b) << 16);
}
__device__ __forceinline__ void split2h(float x, __half& h, __half& l) {
    h = __float2half_rn(x);
    l = __float2half_rn(x - __half2float(h));
}
__device__ __forceinline__ uint32_t pack2h(__half a, __half b) {
    return (uint32_t)__half_as_ushort(a) | ((uint32_t)__half_as_ushort(b) << 16);
}

// W[k][n] -> W^T[n][k]: bf16 hi/lo (z=0,1: Wq,Wk), fp16 (z=2,3: Wv,Wo)
__global__ __launch_bounds__(256) void transpose_split_kernel(const float* __restrict__ Wq,
                                                              const float* __restrict__ Wk,
                                                              const float* __restrict__ Wv,
                                                              const float* __restrict__ Wo)
{
    __shared__ float tile[32][33];
    const int z = blockIdx.z;
    const float* W = (z == 0) ? Wq : (z == 1) ? Wk : (z == 2) ? Wv : Wo;
    const int k0 = blockIdx.y * 32, n0 = blockIdx.x * 32;
#pragma unroll
    for (int r = 0; r < 32; r += 8)
        tile[threadIdx.y + r][threadIdx.x] = W[(size_t)(k0 + threadIdx.y + r) * DD + n0 + threadIdx.x];
    __syncthreads();
#pragma unroll
    for (int r = 0; r < 32; r += 8) {
        const int n = n0 + threadIdx.y + r, k = k0 + threadIdx.x;
        const float w = tile[threadIdx.x][threadIdx.y + r];
        if (z < 2) {
            __nv_bfloat16 h, l;
            split2(w, h, l);
            g_wh[z][(size_t)n * DD + k] = h;
            g_wl[z][(size_t)n * DD + k] = l;
        } else {
            g_wf[z - 2][(size_t)n * DD + k] = __float2half_rn(w);
        }
    }
}

// ====== HMMA GEMM: 128x128 tile, BK=32, 2-stage, 1 sync/chunk ==============
// F16=0: 3-term bf16 split (AhBh + AhBl + AlBh)
// F16=1: 2-term fp16 split (AhBh + AlBh), B pre-rounded to fp16
#define STG 40                          // smem row stride, 16-bit elems
#define ARRB (128*STG*2)                // 10240 B
#define OFF_AH 0
#define OFF_AL (ARRB)
#define OFF_BH (2*ARRB)
#define OFF_BL (3*ARRB)
#define STAGE_B (4*ARRB)                // 40960
#define GSMEM (2*STAGE_B)               // 81920

template<int F16>
__device__ __forceinline__ void split_sts(char* stagebase, int lrow, int lhalf,
                                          const float4* v4)
{
    uint16_t* ah = (uint16_t*)(stagebase + OFF_AH);
    uint16_t* al = (uint16_t*)(stagebase + OFF_AL);
#pragma unroll
    for (int qq = 0; qq < 4; qq++) {
        const float4 v = v4[qq];
        uint2 uh, ul;
        if (F16) {
            __half h0, h1, h2, h3, l0, l1, l2, l3;
            split2h(v.x, h0, l0); split2h(v.y, h1, l1);
            split2h(v.z, h2, l2); split2h(v.w, h3, l3);
            uh.x = pack2h(h0, h1); uh.y = pack2h(h2, h3);
            ul.x = pack2h(l0, l1); ul.y = pack2h(l2, l3);
        } else {
            __nv_bfloat16 h0, h1, h2, h3, l0, l1, l2, l3;
            split2(v.x, h0, l0); split2(v.y, h1, l1);
            split2(v.z, h2, l2); split2(v.w, h3, l3);
            uh.x = pack2(h0, h1); uh.y = pack2(h2, h3);
            ul.x = pack2(l0, l1); ul.y = pack2(l2, l3);
        }
        *(uint2*)(ah + lrow * STG + lhalf + qq * 4) = uh;
        *(uint2*)(al + lrow * STG + lhalf + qq * 4) = ul;
    }
}

// B load: 128 rows x 32 cols of 16-bit = 512 x 16B chunks -> 2 reps x 256 thr
template<int F16>
__device__ __forceinline__ void load_B(uint32_t s, const uint16_t* __restrict__ Bh,
                                       const uint16_t* __restrict__ Bl,
                                       int n0, int k0, int tid)
{
#pragma unroll
    for (int rep = 0; rep < 2; rep++) {
        const int c = tid + rep * 256;
        const int row = c >> 2, kp = (c & 3) * 8;
        cpasync16(s + OFF_BH + (uint32_t)(row * STG + kp) * 2,
                  Bh + (size_t)(n0 + row) * DD + k0 + kp);
    }
    if (!F16) {
#pragma unroll
        for (int rep = 0; rep < 2; rep++) {
            const int c = tid + rep * 256;
            const int row = c >> 2, kp = (c & 3) * 8;
            cpasync16(s + OFF_BL + (uint32_t)(row * STG + kp) * 2,
                      Bl + (size_t)(n0 + row) * DD + k0 + kp);
        }
    }
    cp_commit();
}

template<int SCATTER, int F16>
__device__ __forceinline__ void gemm_core(const float* __restrict__ A,
                                          const uint16_t* __restrict__ Bh,
                                          const uint16_t* __restrict__ Bl,
                                          const float* __restrict__ bias,
                                          float* __restrict__ dst, char* smraw)
{
    const int tid = threadIdx.x;
    const int m0 = blockIdx.y * 128, n0 = blockIdx.x * 128;
    const uint32_t sbase = smem_u32(smraw);

    const int wid = tid >> 5, lane = tid & 31;
    const int wm = (wid >> 2) * 64;       // 0 or 64
    const int wn = (wid & 3) * 32;        // 0,32,64,96
    const int g  = lane >> 2;             // 0..7
    const int q2 = (lane & 3) * 2;        // 0,2,4,6

    const int aRow = wm + (lane & 7) + ((lane >> 3) & 1) * 8;
    const int aColE = (lane >> 4) * 8;
    const int bRow = wn + (lane & 7) + ((lane >> 4) & 1) * 8;
    const int bColE = ((lane >> 3) & 1) * 8;

    const int lrow = tid >> 1, lhalf = (tid & 1) * 16;
    const float* Arow = A + (size_t)(m0 + lrow) * DD + lhalf;

    float acc[4][4][4];
#pragma unroll
    for (int i = 0; i < 4; i++)
#pragma unroll
        for (int j = 0; j < 4; j++)
#pragma unroll
            for (int r = 0; r < 4; r++) acc[i][j][r] = 0.f;

    float4 areg[2][4];

    // ---- prologue: chunk0 A split into stage0, chunk1 A regs, B(0) cp ----
#pragma unroll
    for (int qq = 0; qq < 4; qq++) areg[0][qq] = *(const float4*)(Arow + qq * 4);
    split_sts<F16>(smraw, lrow, lhalf, areg[0]);
#pragma unroll
    for (int qq = 0; qq < 4; qq++) areg[1][qq] = *(const float4*)(Arow + 32 + qq * 4);
    load_B<F16>(sbase, Bh, Bl, n0, 0, tid);

    for (int c = 0; c < 16; c++) {
        cp_wait<0>();           // B(c) fully arrived
        __syncthreads();        // closes iter c-1: split-STS(c) visible, stage (c+1)&1 free

        if (c < 14) {           // prefetch A(c+2) into regs (consumed iter c+1)
            const int k2 = (c + 2) * 32;
#pragma unroll
            for (int qq = 0; qq < 4; qq++)
                areg[c & 1][qq] = *(const float4*)(Arow + k2 + qq * 4);
        }
        if (c < 15) {           // stage (c+1)&1: cp B(c+1) (overlaps MMA) + split A(c+1)
            const int k1 = (c + 1) * 32;
            const uint32_t s = sbase + (uint32_t)((c + 1) & 1) * STAGE_B;
            load_B<F16>(s, Bh, Bl, n0, k1, tid);
            split_sts<F16>(smraw + ((c + 1) & 1) * STAGE_B, lrow, lhalf, areg[(c + 1) & 1]);
        }

        // ---- MMA on stage c&1 ----
        const uint32_t stb = sbase + (uint32_t)(c & 1) * STAGE_B;
        const uint32_t aH = stb + OFF_AH + (uint32_t)(aRow * STG + aColE) * 2;
        const uint32_t aL = stb + OFF_AL + (uint32_t)(aRow * STG + aColE) * 2;
        const uint32_t bH = stb + OFF_BH + (uint32_t)(bRow * STG + bColE) * 2;
        const uint32_t bL = stb + OFF_BL + (uint32_t)(bRow * STG + bColE) * 2;

#pragma unroll
        for (int ks = 0; ks < 32; ks += 16) {
            uint32_t ah4[4][4], al4[4][4], bh4[2][4], bl4[2][4];
#pragma unroll
            for (int i = 0; i < 4; i++)
                ldsm4(ah4[i][0], ah4[i][1], ah4[i][2], ah4[i][3],
                      aH + (uint32_t)(i * 16 * STG + ks) * 2);
#pragma unroll
            for (int jp = 0; jp < 2; jp++)
                ldsm4(bh4[jp][0], bh4[jp][1], bh4[jp][2], bh4[jp][3],
                      bH + (uint32_t)(jp * 16 * STG + ks) * 2);
            if (!F16) {
#pragma unroll
                for (int jp = 0; jp < 2; jp++)
                    ldsm4(bl4[jp][0], bl4[jp][1], bl4[jp][2], bl4[jp][3],
                          bL + (uint32_t)(jp * 16 * STG + ks) * 2);
            }
#pragma unroll
            for (int i = 0; i < 4; i++)
                ldsm4(al4[i][0], al4[i][1], al4[i][2], al4[i][3],
                      aL + (uint32_t)(i * 16 * STG + ks) * 2);

#pragma unroll
            for (int i = 0; i < 4; i++)
#pragma unroll
                for (int j = 0; j < 4; j++) {
                    const int jp = j >> 1, jo = (j & 1) * 2;
                    mma_any<F16>(acc[i][j][0], acc[i][j][1], acc[i][j][2], acc[i][j][3],
                                 ah4[i][0], ah4[i][1], ah4[i][2], ah4[i][3],
                                 bh4[jp][jo], bh4[jp][jo + 1]);
                }
            if (!F16) {
#pragma unroll
                for (int i = 0; i < 4; i++)
#pragma unroll
                    for (int j = 0; j < 4; j++) {
                        const int jp = j >> 1, jo = (j & 1) * 2;
                        mma_any<F16>(acc[i][j][0], acc[i][j][1], acc[i][j][2], acc[i][j][3],
                                     ah4[i][0], ah4[i][1], ah4[i][2], ah4[i][3],
                                     bl4[jp][jo], bl4[jp][jo + 1]);
                    }
            }
#pragma unroll
            for (int i = 0; i < 4; i++)
#pragma unroll
                for (int j = 0; j < 4; j++) {
                    const int jp = j >> 1, jo = (j & 1) * 2;
                    mma_any<F16>(acc[i][j][0], acc[i][j][1], acc[i][j][2], acc[i][j][3],
                                 al4[i][0], al4[i][1], al4[i][2], al4[i][3],
                                 bh4[jp][jo], bh4[jp][jo + 1]);
                }
        }
    }

    // epilogue
#pragma unroll
    for (int i = 0; i < 4; i++) {
#pragma unroll
        for (int j = 0; j < 4; j++) {
            const int gm0 = m0 + wm + i * 16 + g;
            const int gn  = n0 + wn + j * 8 + q2;
            const float b0 = bias[gn], b1 = bias[gn + 1];
            const float v0 = acc[i][j][0] + b0, v1 = acc[i][j][1] + b1;
            const float v2 = acc[i][j][2] + b0, v3 = acc[i][j][3] + b1;
            if (SCATTER == 0) {
                float* p0 = dst + (size_t)gm0 * DD + gn;
                p0[0] = v0; p0[1] = v1;
                float* p1 = dst + (size_t)(gm0 + 8) * DD + gn;
                p1[0] = v2; p1[1] = v3;
            } else {
                const int h = gn >> 6, dk = gn & 63;
                {
                    const int b = gm0 >> 11, l = gm0 & 2047;
                    float* p = dst + (((size_t)(b * HH + h)) * LL + l) * DKK + dk;
                    p[0] = v0; p[1] = v1;
                }
                {
                    const int gm1 = gm0 + 8;
                    const int b = gm1 >> 11, l = gm1 & 2047;
                    float* p = dst + (((size_t)(b * HH + h)) * LL + l) * DKK + dk;
                    p[0] = v2; p[1] = v3;
                }
            }
        }
    }
}

__global__ __launch_bounds__(256, 1) void hgemm_qk(const float* __restrict__ q,
                                                   const float* __restrict__ k,
                                                   const float* __restrict__ bq,
                                                   const float* __restrict__ bk)
{
    extern __shared__ char smraw[];
    const int z = blockIdx.z;
    gemm_core<1, 0>((z == 0) ? q : k,
                    (const uint16_t*)g_wh[z], (const uint16_t*)g_wl[z],
                    (z == 0) ? bq : bk, (z == 0) ? g_q : g_k, smraw);
}

__global__ __launch_bounds__(256, 1) void hgemm_v(const float* __restrict__ v,
                                                  const float* __restrict__ bv)
{
    extern __shared__ char smraw[];
    gemm_core<1, 1>(v, (const uint16_t*)g_wf[0], (const uint16_t*)g_wf[0],
                    bv, g_v, smraw);
}

__global__ __launch_bounds__(256, 1) void hgemm_out(const float* __restrict__ bo,
                                                    float* __restrict__ outp)
{
    extern __shared__ char smraw[];
    gemm_core<0, 1>((const float*)g_ctx, (const uint16_t*)g_wf[1], (const uint16_t*)g_wf[1],
                    bo, outp, smraw);
}

// =========================== non-GEMM kernels ==============================
__global__ __launch_bounds__(256) void probe_kernel(const int* __restrict__ idx)
{
    const int w = (blockIdx.x * blockDim.x + threadIdx.x) >> 5;
    const int lane = threadIdx.x & 31;
    if (w >= BB * HH * LL) return;
    const int l = w & (LL - 1);
    const int bh = w >> 11;

    const float* qrow = g_q + (size_t)(bh * LL + l) * DKK;
    const float2 qv = *(const float2*)(qrow + lane * 2);
    const float* kbase = g_k + (size_t)bh * LL * DKK;
    const int* ip = idx + l * UU;
    const int myidx = (lane < UU) ? ip[lane] : 0;

    float mx = -INFINITY, sm = 0.f;
#pragma unroll 4
    for (int s = 0; s < UU; s++) {
        const int j = __shfl_sync(0xffffffffu, myidx, s);
        const float2 kk = *(const float2*)(kbase + (size_t)j * DKK + lane * 2);
        float p = qv.x * kk.x + qv.y * kk.y;
#pragma unroll
        for (int o = 16; o > 0; o >>= 1) p += __shfl_xor_sync(0xffffffffu, p, o);
        mx = fmaxf(mx, p);
        sm += p;
    }
    if (lane == 0) g_m[w] = mx - sm * (1.0f / LL);
}

__global__ __launch_bounds__(256) void topk_kernel()
{
    __shared__ float swv[8];
    __shared__ int   swi[8];
    __shared__ int   swin;
    const int bh = blockIdx.x;
    const int t = threadIdx.x;
    const int wid = t >> 5, lane = t & 31;

    float v[8];
#pragma unroll
    for (int j = 0; j < 8; j++) v[j] = g_m[(size_t)bh * LL + j * 256 + t];

    for (int iter = 0; iter < UU; iter++) {
        float bv = v[0]; int bj = 0;
#pragma unroll
        for (int j = 1; j < 8; j++) if (v[j] > bv) { bv = v[j]; bj = j; }
        int bi = bj * 256 + t;
#pragma unroll
        for (int o = 16; o > 0; o >>= 1) {
            const float ov = __shfl_xor_sync(0xffffffffu, bv, o);
            const int   oi = __shfl_xor_sync(0xffffffffu, bi, o);
            if (ov > bv || (ov == bv && oi < bi)) { bv = ov; bi = oi; }
        }
        if (lane == 0) { swv[wid] = bv; swi[wid] = bi; }
        __syncthreads();
        if (t == 0) {
            float mv = swv[0]; int mi = swi[0];
#pragma unroll
            for (int w = 1; w < 8; w++)
                if (swv[w] > mv || (swv[w] == mv && swi[w] < mi)) { mv = swv[w]; mi = swi[w]; }
            g_top[bh * UU + iter] = mi;
            swin = mi;
        }
        __syncthreads();
        const int win = swin;
        if ((win & 255) == t) v[win >> 8] = -INFINITY;
    }
}

#define QG 4
__global__ __launch_bounds__(256) void attn_kernel()
{
    __shared__ float qs[QG][DKK];
    __shared__ float sc[QG][LL];
    __shared__ float red[256];
    __shared__ int   pos_s[QG];

    const int bh = blockIdx.x / (UU / QG);
    const int grp = blockIdx.x % (UU / QG);
    const int t = threadIdx.x;
    const int wid = t >> 5, lane = t & 31;

    const float* kb = g_k + (size_t)bh * LL * DKK;
    const float* vb = g_v + (size_t)bh * LL * DKK;

    {
        const int u = t >> 6, d = t & 63;
        const int p = g_top[bh * UU + grp * QG + u];
        if (d == 0) pos_s[u] = p;
        qs[u][d] = g_q[((size_t)bh * LL + p) * DKK + d];
    }
    __syncthreads();

    const float scale = rsqrtf((float)DD);

    float lmax[QG];
#pragma unroll
    for (int u = 0; u < QG; u++) lmax[u] = -INFINITY;

    for (int j = t; j < LL; j += 256) {
        const float* kr = kb + (size_t)j * DKK;
        float dot[QG];
#pragma unroll
        for (int u = 0; u < QG; u++) dot[u] = 0.f;
#pragma unroll
        for (int d4 = 0; d4 < 16; d4++) {
            float4 kk = *(const float4*)(kr + d4 * 4);
#pragma unroll
            for (int u = 0; u < QG; u++) {
                dot[u] += qs[u][d4 * 4] * kk.x + qs[u][d4 * 4 + 1] * kk.y +
                          qs[u][d4 * 4 + 2] * kk.z + qs[u][d4 * 4 + 3] * kk.w;
            }
        }
#pragma unroll
        for (int u = 0; u < QG; u++) {
            const float s = (j > pos_s[u]) ? -INFINITY : dot[u] * scale;
            sc[u][j] = s;
            lmax[u] = fmaxf(lmax[u], s);
        }
    }
#pragma unroll
    for (int u = 0; u < QG; u++) {
        float m = lmax[u];
#pragma unroll
        for (int o = 16; o > 0; o >>= 1) m = fmaxf(m, __shfl_xor_sync(0xffffffffu, m, o));
        if (lane == 0) red[u * 8 + wid] = m;
    }
    __syncthreads();
    float mx[QG];
#pragma unroll
    for (int u = 0; u < QG; u++) {
        float m = -INFINITY;
#pragma unroll
        for (int w = 0; w < 8; w++) m = fmaxf(m, red[u * 8 + w]);
        mx[u] = m;
    }
    __syncthreads();

    float lsum[QG];
#pragma unroll
    for (int u = 0; u < QG; u++) lsum[u] = 0.f;
    for (int j = t; j < LL; j += 256) {
#pragma unroll
        for (int u = 0; u < QG; u++) {
            const float p = __expf(sc[u][j] - mx[u]);
            sc[u][j] = p;
            lsum[u] += p;
        }
    }
#pragma unroll
    for (int u = 0; u < QG; u++) {
        float s = lsum[u];
#pragma unroll
        for (int o = 16; o > 0; o >>= 1) s += __shfl_xor_sync(0xffffffffu, s, o);
        if (lane == 0) red[u * 8 + wid] = s;
    }
    __syncthreads();
    float inv[QG];
#pragma unroll
    for (int u = 0; u < QG; u++) {
        float s = 0.f;
#pragma unroll
        for (int w = 0; w < 8; w++) s += red[u * 8 + w];
        inv[u] = 1.0f / s;
    }
    __syncthreads();

    const int d = t & 63, g4 = t >> 6;
    float acc[QG];
#pragma unroll
    for (int u = 0; u < QG; u++) acc[u] = 0.f;
    const int j0 = g4 * (LL / 4), j1 = j0 + (LL / 4);
    for (int j = j0; j < j1; j++) {
        const float v = vb[(size_t)j * DKK + d];
#pragma unroll
        for (int u = 0; u < QG; u++) acc[u] += sc[u][j] * v;
    }
#pragma unroll
    for (int u = 0; u < QG; u++) {
        red[t] = acc[u];
        __syncthreads();
        if (t < DKK) {
            const float o = (red[t] + red[t + 64] + red[t + 128] + red[t + 192]) * inv[u];
            g_att[(size_t)(bh * UU + grp * QG + u) * DKK + t] = o;
        }
        __syncthreads();
    }
}

// ---- cumsum, 3-phase ------------------------------------------------------
__global__ __launch_bounds__(256) void cumsum_p1()
{
    const int bh = blockIdx.x, ch = blockIdx.y;
    const int t = threadIdx.x;
    const int d = t & 63, seg = t >> 6;
    const float* vb = g_v + (size_t)bh * LL * DKK;
    const int l0 = ch * 128 + seg * 32;
    float s = 0.f;
#pragma unroll 4
    for (int l = l0; l < l0 + 32; l++) s += vb[(size_t)l * DKK + d];
    g_segsum[bh][ch][seg][d] = s;
}
__global__ __launch_bounds__(64) void cumsum_p2()
{
    const int bh = blockIdx.x, d = threadIdx.x;
    float run = 0.f;
#pragma unroll
    for (int ch = 0; ch < 16; ch++) {
        g_chpre[bh][ch][d] = run;
        run += g_segsum[bh][ch][0][d] + g_segsum[bh][ch][1][d] +
               g_segsum[bh][ch][2][d] + g_segsum[bh][ch][3][d];
    }
}
__global__ __launch_bounds__(256) void cumsum_p3()
{
    const int bh = blockIdx.x, ch = blockIdx.y;
    const int b = bh >> 3, h = bh & 7;
    const int t = threadIdx.x;
    const int d = t & 63, seg = t >> 6;
    const float* vb = g_v + (size_t)bh * LL * DKK;

    float off = g_chpre[bh][ch][d];
    for (int s = 0; s < seg; s++) off += g_segsum[bh][ch][s][d];

    const int l0 = ch * 128 + seg * 32;
    float acc = off;
    float* cb = g_ctx + (size_t)b * LL * DD + h * DKK;
#pragma unroll 4
    for (int l = l0; l < l0 + 32; l++) {
        acc += vb[(size_t)l * DKK + d];
        cb[(size_t)l * DD + d] = acc;
    }
}

__global__ void scatter_kernel()
{
    const int i = blockIdx.x * blockDim.x + threadIdx.x;
    if (i >= BB * HH * UU * DKK) return;
    const int d = i & 63;
    const int r = i >> 6;
    const int bh = r / UU;
    const int b = bh >> 3, h = bh & 7;
    const int pos = g_top[r];
    g_ctx[((size_t)b * LL + pos) * DD + h * DKK + d] = g_att[i];
}

// ---------------------------------------------------------------------------
extern "C" void kernel_launch(void* const* d_in, const int* in_sizes, int n_in,
                              void* d_out, int out_size)
{
    const float* queries = (const float*)d_in[0];
    const float* keys    = (const float*)d_in[1];
    const float* values  = (const float*)d_in[2];
    const int*   index_sample = (const int*)d_in[3];
    const float* Wq = (const float*)d_in[4];
    const float* bq = (const float*)d_in[5];
    const float* Wk = (const float*)d_in[6];
    const float* bk = (const float*)d_in[7];
    const float* Wv = (const float*)d_in[8];
    const float* bv = (const float*)d_in[9];
    const float* Wo = (const float*)d_in[10];
    const float* bo = (const float*)d_in[11];
    float* out = (float*)d_out;

    cudaFuncSetAttribute(hgemm_qk,  cudaFuncAttributeMaxDynamicSharedMemorySize, GSMEM);
    cudaFuncSetAttribute(hgemm_v,   cudaFuncAttributeMaxDynamicSharedMemorySize, GSMEM);
    cudaFuncSetAttribute(hgemm_out, cudaFuncAttributeMaxDynamicSharedMemorySize, GSMEM);

    transpose_split_kernel<<<dim3(16, 16, 4), dim3(32, 8)>>>(Wq, Wk, Wv, Wo);

    hgemm_qk<<<dim3(DD / 128, MTOT / 128, 2), 256, GSMEM>>>(queries, keys, bq, bk);
    hgemm_v<<<dim3(DD / 128, MTOT / 128, 1), 256, GSMEM>>>(values, bv);

    probe_kernel<<<(BB * HH * LL * 32) / 256, 256>>>(index_sample);
    topk_kernel<<<BH, 256>>>();
    attn_kernel<<<BH * (UU / QG), 256>>>();
    cumsum_p1<<<dim3(BH, 16), 256>>>();
    cumsum_p2<<<BH, 64>>>();
    cumsum_p3<<<dim3(BH, 16), 256>>>();
    scatter_kernel<<<(BB * HH * UU * DKK + 255) / 256, 256>>>();

    hgemm_out<<<dim3(DD / 128, MTOT / 128, 1), 256, GSMEM>>>(bo, out);
}

// round 11
// speedup vs baseline: 1.3667x; 1.2226x over previous
#include <cuda_runtime.h>
#include <cuda_bf16.h>
#include <cuda_fp16.h>
#include <math.h>
#include <stdint.h>

// Problem constants
#define BB 4
#define LL 2048
#define DD 512
#define HH 8
#define DKK 64
#define UU 24
#define BH (BB*HH)
#define MTOT (BB*LL)     // 8192 rows per GEMM

// ---------------- scratch (device globals; no allocation allowed) ----------
__device__ float g_q[BB*HH*LL*DKK];     // (B,H,L,DK)
__device__ float g_k[BB*HH*LL*DKK];
__device__ float g_v[BB*HH*LL*DKK];
__device__ float g_m[BB*HH*LL];
__device__ int   g_top[BB*HH*UU];
__device__ float g_att[BB*HH*UU*DKK];
__device__ float g_ctx[BB*LL*DD];       // (b, l, h*DK+dk)

// pre-split transposed weights W^T[n][k]: bf16 hi/lo for Wq,Wk; fp16 for Wv,Wo
__device__ __nv_bfloat16 g_wh[2][DD*DD];
__device__ __nv_bfloat16 g_wl[2][DD*DD];
__device__ __half        g_wf[2][DD*DD];

// cumsum scratch
__device__ float g_segsum[BH][16][4][DKK];
__device__ float g_chpre[BH][16][DKK];

// =========================== helpers =======================================
__device__ __forceinline__ uint32_t smem_u32(const void* p) {
    uint32_t a;
    asm("{ .reg .u64 t; cvta.to.shared.u64 t, %1; cvt.u32.u64 %0, t; }"
        : "=r"(a) : "l"(p));
    return a;
}
__device__ __forceinline__ void cpasync16(uint32_t saddr, const void* gptr) {
    asm volatile("cp.async.cg.shared.global [%0], [%1], 16;"
                 :: "r"(saddr), "l"(__cvta_generic_to_global(gptr)) : "memory");
}
__device__ __forceinline__ void cp_commit() {
    asm volatile("cp.async.commit_group;" ::: "memory");
}
template<int N>
__device__ __forceinline__ void cp_wait() {
    asm volatile("cp.async.wait_group %0;" :: "n"(N) : "memory");
}
template<int F16>
__device__ __forceinline__ void mma_any(float& c0, float& c1, float& c2, float& c3,
                                        uint32_t a0, uint32_t a1, uint32_t a2, uint32_t a3,
                                        uint32_t b0, uint32_t b1) {
    if (F16)
        asm volatile("mma.sync.aligned.m16n8k16.row.col.f32.f16.f16.f32 "
                     "{%0,%1,%2,%3}, {%4,%5,%6,%7}, {%8,%9}, {%0,%1,%2,%3};"
                     : "+f"(c0), "+f"(c1), "+f"(c2), "+f"(c3)
                     : "r"(a0), "r"(a1), "r"(a2), "r"(a3), "r"(b0), "r"(b1));
    else
        asm volatile("mma.sync.aligned.m16n8k16.row.col.f32.bf16.bf16.f32 "
                     "{%0,%1,%2,%3}, {%4,%5,%6,%7}, {%8,%9}, {%0,%1,%2,%3};"
                     : "+f"(c0), "+f"(c1), "+f"(c2), "+f"(c3)
                     : "r"(a0), "r"(a1), "r"(a2), "r"(a3), "r"(b0), "r"(b1));
}
__device__ __forceinline__ void ldsm4(uint32_t& r0, uint32_t& r1, uint32_t& r2, uint32_t& r3,
                                      uint32_t addr) {
    asm volatile("ldmatrix.sync.aligned.m8n8.x4.shared.b16 {%0,%1,%2,%3}, [%4];"
                 : "=r"(r0), "=r"(r1), "=r"(r2), "=r"(r3) : "r"(addr));
}
__device__ __forceinline__ void split2(float x, __nv_bfloat16& h, __nv_bfloat16& l) {
    h = __float2bfloat16_rn(x);
    l = __float2bfloat16_rn(x - __bfloat162float(h));
}
__device__ __forceinline__ uint32_t pack2(__nv_bfloat16 a, __nv_bfloat16 b) {
    return (uint32_t)__bfloat16_as_ushort(a) | ((uint32_t)__bfloat16_as_ushort(b) << 16);
}
__device__ __forceinline__ void split2h(float x, __half& h, __half& l) {
    h = __float2half_rn(x);
    l = __float2half_rn(x - __half2float(h));
}
__device__ __forceinline__ uint32_t pack2h(__half a, __half b) {
    return (uint32_t)__half_as_ushort(a) | ((uint32_t)__half_as_ushort(b) << 16);
}

// W[k][n] -> W^T[n][k]: bf16 hi/lo (z=0,1: Wq,Wk), fp16 (z=2,3: Wv,Wo)
__global__ __launch_bounds__(256) void transpose_split_kernel(const float* __restrict__ Wq,
                                                              const float* __restrict__ Wk,
                                                              const float* __restrict__ Wv,
                                                              const float* __restrict__ Wo)
{
    __shared__ float tile[32][33];
    const int z = blockIdx.z;
    const float* W = (z == 0) ? Wq : (z == 1) ? Wk : (z == 2) ? Wv : Wo;
    const int k0 = blockIdx.y * 32, n0 = blockIdx.x * 32;
#pragma unroll
    for (int r = 0; r < 32; r += 8)
        tile[threadIdx.y + r][threadIdx.x] = W[(size_t)(k0 + threadIdx.y + r) * DD + n0 + threadIdx.x];
    __syncthreads();
#pragma unroll
    for (int r = 0; r < 32; r += 8) {
        const int n = n0 + threadIdx.y + r, k = k0 + threadIdx.x;
        const float w = tile[threadIdx.x][threadIdx.y + r];
        if (z < 2) {
            __nv_bfloat16 h, l;
            split2(w, h, l);
            g_wh[z][(size_t)n * DD + k] = h;
            g_wl[z][(size_t)n * DD + k] = l;
        } else {
            g_wf[z - 2][(size_t)n * DD + k] = __float2half_rn(w);
        }
    }
}

// ====== HMMA GEMM: 128x128 tile, BK=32, 2-stage, 1 sync/chunk, occ=2 =======
// F16=0: 3-term bf16 split (AhBh + AhBl + AlBh)
// F16=1: 2-term fp16 split (AhBh + AlBh), B pre-rounded to fp16
#define STG 40                          // smem row stride, 16-bit elems
#define ARRB (128*STG*2)                // 10240 B
#define OFF_AH 0
#define OFF_AL (ARRB)
#define OFF_BH (2*ARRB)
#define OFF_BL (3*ARRB)
#define STAGE_B (4*ARRB)                // 40960
#define GSMEM (2*STAGE_B)               // 81920 -> 2 CTAs/SM = 160 KB

template<int F16>
__device__ __forceinline__ void split_sts(char* stagebase, int lrow, int lhalf,
                                          const float4* v4)
{
    uint16_t* ah = (uint16_t*)(stagebase + OFF_AH);
    uint16_t* al = (uint16_t*)(stagebase + OFF_AL);
#pragma unroll
    for (int qq = 0; qq < 4; qq++) {
        const float4 v = v4[qq];
        uint2 uh, ul;
        if (F16) {
            __half h0, h1, h2, h3, l0, l1, l2, l3;
            split2h(v.x, h0, l0); split2h(v.y, h1, l1);
            split2h(v.z, h2, l2); split2h(v.w, h3, l3);
            uh.x = pack2h(h0, h1); uh.y = pack2h(h2, h3);
            ul.x = pack2h(l0, l1); ul.y = pack2h(l2, l3);
        } else {
            __nv_bfloat16 h0, h1, h2, h3, l0, l1, l2, l3;
            split2(v.x, h0, l0); split2(v.y, h1, l1);
            split2(v.z, h2, l2); split2(v.w, h3, l3);
            uh.x = pack2(h0, h1); uh.y = pack2(h2, h3);
            ul.x = pack2(l0, l1); ul.y = pack2(l2, l3);
        }
        *(uint2*)(ah + lrow * STG + lhalf + qq * 4) = uh;
        *(uint2*)(al + lrow * STG + lhalf + qq * 4) = ul;
    }
}

// B load: 128 rows x 32 cols of 16-bit = 512 x 16B chunks -> 2 reps x 256 thr
template<int F16>
__device__ __forceinline__ void load_B(uint32_t s, const uint16_t* __restrict__ Bh,
                                       const uint16_t* __restrict__ Bl,
                                       int n0, int k0, int tid)
{
#pragma unroll
    for (int rep = 0; rep < 2; rep++) {
        const int c = tid + rep * 256;
        const int row = c >> 2, kp = (c & 3) * 8;
        cpasync16(s + OFF_BH + (uint32_t)(row * STG + kp) * 2,
                  Bh + (size_t)(n0 + row) * DD + k0 + kp);
    }
    if (!F16) {
#pragma unroll
        for (int rep = 0; rep < 2; rep++) {
            const int c = tid + rep * 256;
            const int row = c >> 2, kp = (c & 3) * 8;
            cpasync16(s + OFF_BL + (uint32_t)(row * STG + kp) * 2,
                      Bl + (size_t)(n0 + row) * DD + k0 + kp);
        }
    }
    cp_commit();
}

template<int SCATTER, int F16>
__device__ __forceinline__ void gemm_core(const float* __restrict__ A,
                                          const uint16_t* __restrict__ Bh,
                                          const uint16_t* __restrict__ Bl,
                                          const float* __restrict__ bias,
                                          float* __restrict__ dst, char* smraw,
                                          int m0, int n0)
{
    const int tid = threadIdx.x;
    const uint32_t sbase = smem_u32(smraw);

    const int wid = tid >> 5, lane = tid & 31;
    const int wm = (wid >> 2) * 64;       // 0 or 64
    const int wn = (wid & 3) * 32;        // 0,32,64,96
    const int g  = lane >> 2;             // 0..7
    const int q2 = (lane & 3) * 2;        // 0,2,4,6

    const int aRow = wm + (lane & 7) + ((lane >> 3) & 1) * 8;
    const int aColE = (lane >> 4) * 8;
    const int bRow = wn + (lane & 7) + ((lane >> 4) & 1) * 8;
    const int bColE = ((lane >> 3) & 1) * 8;

    const int lrow = tid >> 1, lhalf = (tid & 1) * 16;
    const float* Arow = A + (size_t)(m0 + lrow) * DD + lhalf;

    float acc[4][4][4];
#pragma unroll
    for (int i = 0; i < 4; i++)
#pragma unroll
        for (int j = 0; j < 4; j++)
#pragma unroll
            for (int r = 0; r < 4; r++) acc[i][j][r] = 0.f;

    float4 areg[4];   // single buffer (register budget for occ=2)

    // ---- prologue: chunk0 split to stage0, B(0) cp ----
#pragma unroll
    for (int qq = 0; qq < 4; qq++) areg[qq] = *(const float4*)(Arow + qq * 4);
    split_sts<F16>(smraw, lrow, lhalf, areg);
    load_B<F16>(sbase, Bh, Bl, n0, 0, tid);

    for (int c = 0; c < 16; c++) {
        cp_wait<0>();           // B(c) arrived
        __syncthreads();        // split-STS(c) visible; both stages' old readers done

        if (c < 15) {           // issue A(c+1) LDG + B(c+1) cp (overlap MMA below)
            const int k1 = (c + 1) * 32;
#pragma unroll
            for (int qq = 0; qq < 4; qq++)
                areg[qq] = *(const float4*)(Arow + k1 + qq * 4);
            load_B<F16>(sbase + (uint32_t)((c + 1) & 1) * STAGE_B, Bh, Bl, n0, k1, tid);
        }

        // ---- MMA on stage c&1 ----
        const uint32_t stb = sbase + (uint32_t)(c & 1) * STAGE_B;
        const uint32_t aH = stb + OFF_AH + (uint32_t)(aRow * STG + aColE) * 2;
        const uint32_t aL = stb + OFF_AL + (uint32_t)(aRow * STG + aColE) * 2;
        const uint32_t bH = stb + OFF_BH + (uint32_t)(bRow * STG + bColE) * 2;
        const uint32_t bL = stb + OFF_BL + (uint32_t)(bRow * STG + bColE) * 2;

#pragma unroll
        for (int ks = 0; ks < 32; ks += 16) {
            uint32_t ah4[4][4], al4[4][4], bh4[2][4], bl4[2][4];
#pragma unroll
            for (int i = 0; i < 4; i++)
                ldsm4(ah4[i][0], ah4[i][1], ah4[i][2], ah4[i][3],
                      aH + (uint32_t)(i * 16 * STG + ks) * 2);
#pragma unroll
            for (int jp = 0; jp < 2; jp++)
                ldsm4(bh4[jp][0], bh4[jp][1], bh4[jp][2], bh4[jp][3],
                      bH + (uint32_t)(jp * 16 * STG + ks) * 2);
            if (!F16) {
#pragma unroll
                for (int jp = 0; jp < 2; jp++)
                    ldsm4(bl4[jp][0], bl4[jp][1], bl4[jp][2], bl4[jp][3],
                          bL + (uint32_t)(jp * 16 * STG + ks) * 2);
            }
#pragma unroll
            for (int i = 0; i < 4; i++)
                ldsm4(al4[i][0], al4[i][1], al4[i][2], al4[i][3],
                      aL + (uint32_t)(i * 16 * STG + ks) * 2);

#pragma unroll
            for (int i = 0; i < 4; i++)
#pragma unroll
                for (int j = 0; j < 4; j++) {
                    const int jp = j >> 1, jo = (j & 1) * 2;
                    mma_any<F16>(acc[i][j][0], acc[i][j][1], acc[i][j][2], acc[i][j][3],
                                 ah4[i][0], ah4[i][1], ah4[i][2], ah4[i][3],
                                 bh4[jp][jo], bh4[jp][jo + 1]);
                }
            if (!F16) {
#pragma unroll
                for (int i = 0; i < 4; i++)
#pragma unroll
                    for (int j = 0; j < 4; j++) {
                        const int jp = j >> 1, jo = (j & 1) * 2;
                        mma_any<F16>(acc[i][j][0], acc[i][j][1], acc[i][j][2], acc[i][j][3],
                                     ah4[i][0], ah4[i][1], ah4[i][2], ah4[i][3],
                                     bl4[jp][jo], bl4[jp][jo + 1]);
                    }
            }
#pragma unroll
            for (int i = 0; i < 4; i++)
#pragma unroll
                for (int j = 0; j < 4; j++) {
                    const int jp = j >> 1, jo = (j & 1) * 2;
                    mma_any<F16>(acc[i][j][0], acc[i][j][1], acc[i][j][2], acc[i][j][3],
                                 al4[i][0], al4[i][1], al4[i][2], al4[i][3],
                                 bh4[jp][jo], bh4[jp][jo + 1]);
                }
        }

        // split A(c+1) into stage (c+1)&1 (after MMA: LDG latency was covered)
        if (c < 15)
            split_sts<F16>(smraw + ((c + 1) & 1) * STAGE_B, lrow, lhalf, areg);
    }

    // epilogue
#pragma unroll
    for (int i = 0; i < 4; i++) {
#pragma unroll
        for (int j = 0; j < 4; j++) {
            const int gm0 = m0 + wm + i * 16 + g;
            const int gn  = n0 + wn + j * 8 + q2;
            const float b0 = bias[gn], b1 = bias[gn + 1];
            const float v0 = acc[i][j][0] + b0, v1 = acc[i][j][1] + b1;
            const float v2 = acc[i][j][2] + b0, v3 = acc[i][j][3] + b1;
            if (SCATTER == 0) {
                float* p0 = dst + (size_t)gm0 * DD + gn;
                p0[0] = v0; p0[1] = v1;
                float* p1 = dst + (size_t)(gm0 + 8) * DD + gn;
                p1[0] = v2; p1[1] = v3;
            } else {
                const int h = gn >> 6, dk = gn & 63;
                {
                    const int b = gm0 >> 11, l = gm0 & 2047;
                    float* p = dst + (((size_t)(b * HH + h)) * LL + l) * DKK + dk;
                    p[0] = v0; p[1] = v1;
                }
                {
                    const int gm1 = gm0 + 8;
                    const int b = gm1 >> 11, l = gm1 & 2047;
                    float* p = dst + (((size_t)(b * HH + h)) * LL + l) * DKK + dk;
                    p[0] = v2; p[1] = v3;
                }
            }
        }
    }
}

// merged Q/K/V projections: z=0,1 -> bf16 3-term; z=2 -> fp16 2-term
__global__ __launch_bounds__(256, 2) void hgemm_qkv(const float* __restrict__ q,
                                                    const float* __restrict__ k,
                                                    const float* __restrict__ v,
                                                    const float* __restrict__ bq,
                                                    const float* __restrict__ bk,
                                                    const float* __restrict__ bv)
{
    extern __shared__ char smraw[];
    const int z = blockIdx.z;
    const int m0 = blockIdx.y * 128, n0 = blockIdx.x * 128;
    if (z < 2) {
        gemm_core<1, 0>((z == 0) ? q : k,
                        (const uint16_t*)g_wh[z], (const uint16_t*)g_wl[z],
                        (z == 0) ? bq : bk, (z == 0) ? g_q : g_k, smraw, m0, n0);
    } else {
        gemm_core<1, 1>(v, (const uint16_t*)g_wf[0], (const uint16_t*)g_wf[0],
                        bv, g_v, smraw, m0, n0);
    }
}

__global__ __launch_bounds__(256, 2) void hgemm_out(const float* __restrict__ bo,
                                                    float* __restrict__ outp)
{
    extern __shared__ char smraw[];
    gemm_core<0, 1>((const float*)g_ctx, (const uint16_t*)g_wf[1], (const uint16_t*)g_wf[1],
                    bo, outp, smraw, blockIdx.y * 128, blockIdx.x * 128);
}

// =========================== non-GEMM kernels ==============================
__global__ __launch_bounds__(256) void probe_kernel(const int* __restrict__ idx)
{
    const int w = (blockIdx.x * blockDim.x + threadIdx.x) >> 5;
    const int lane = threadIdx.x & 31;
    if (w >= BB * HH * LL) return;
    const int l = w & (LL - 1);
    const int bh = w >> 11;

    const float* qrow = g_q + (size_t)(bh * LL + l) * DKK;
    const float2 qv = *(const float2*)(qrow + lane * 2);
    const float* kbase = g_k + (size_t)bh * LL * DKK;
    const int* ip = idx + l * UU;
    const int myidx = (lane < UU) ? ip[lane] : 0;

    float mx = -INFINITY, sm = 0.f;
#pragma unroll 4
    for (int s = 0; s < UU; s++) {
        const int j = __shfl_sync(0xffffffffu, myidx, s);
        const float2 kk = *(const float2*)(kbase + (size_t)j * DKK + lane * 2);
        float p = qv.x * kk.x + qv.y * kk.y;
#pragma unroll
        for (int o = 16; o > 0; o >>= 1) p += __shfl_xor_sync(0xffffffffu, p, o);
        mx = fmaxf(mx, p);
        sm += p;
    }
    if (lane == 0) g_m[w] = mx - sm * (1.0f / LL);
}

__global__ __launch_bounds__(256) void topk_kernel()
{
    __shared__ float swv[8];
    __shared__ int   swi[8];
    __shared__ int   swin;
    const int bh = blockIdx.x;
    const int t = threadIdx.x;
    const int wid = t >> 5, lane = t & 31;

    float v[8];
#pragma unroll
    for (int j = 0; j < 8; j++) v[j] = g_m[(size_t)bh * LL + j * 256 + t];

    for (int iter = 0; iter < UU; iter++) {
        float bv = v[0]; int bj = 0;
#pragma unroll
        for (int j = 1; j < 8; j++) if (v[j] > bv) { bv = v[j]; bj = j; }
        int bi = bj * 256 + t;
#pragma unroll
        for (int o = 16; o > 0; o >>= 1) {
            const float ov = __shfl_xor_sync(0xffffffffu, bv, o);
            const int   oi = __shfl_xor_sync(0xffffffffu, bi, o);
            if (ov > bv || (ov == bv && oi < bi)) { bv = ov; bi = oi; }
        }
        if (lane == 0) { swv[wid] = bv; swi[wid] = bi; }
        __syncthreads();
        if (t == 0) {
            float mv = swv[0]; int mi = swi[0];
#pragma unroll
            for (int w = 1; w < 8; w++)
                if (swv[w] > mv || (swv[w] == mv && swi[w] < mi)) { mv = swv[w]; mi = swi[w]; }
            g_top[bh * UU + iter] = mi;
            swin = mi;
        }
        __syncthreads();
        const int win = swin;
        if ((win & 255) == t) v[win >> 8] = -INFINITY;
    }
}

#define QG 4
__global__ __launch_bounds__(256) void attn_kernel()
{
    __shared__ float qs[QG][DKK];
    __shared__ float sc[QG][LL];
    __shared__ float red[256];
    __shared__ int   pos_s[QG];

    const int bh = blockIdx.x / (UU / QG);
    const int grp = blockIdx.x % (UU / QG);
    const int t = threadIdx.x;
    const int wid = t >> 5, lane = t & 31;

    const float* kb = g_k + (size_t)bh * LL * DKK;
    const float* vb = g_v + (size_t)bh * LL * DKK;

    {
        const int u = t >> 6, d = t & 63;
        const int p = g_top[bh * UU + grp * QG + u];
        if (d == 0) pos_s[u] = p;
        qs[u][d] = g_q[((size_t)bh * LL + p) * DKK + d];
    }
    __syncthreads();

    const float scale = rsqrtf((float)DD);

    float lmax[QG];
#pragma unroll
    for (int u = 0; u < QG; u++) lmax[u] = -INFINITY;

    for (int j = t; j < LL; j += 256) {
        const float* kr = kb + (size_t)j * DKK;
        float dot[QG];
#pragma unroll
        for (int u = 0; u < QG; u++) dot[u] = 0.f;
#pragma unroll
        for (int d4 = 0; d4 < 16; d4++) {
            float4 kk = *(const float4*)(kr + d4 * 4);
#pragma unroll
            for (int u = 0; u < QG; u++) {
                dot[u] += qs[u][d4 * 4] * kk.x + qs[u][d4 * 4 + 1] * kk.y +
                          qs[u][d4 * 4 + 2] * kk.z + qs[u][d4 * 4 + 3] * kk.w;
            }
        }
#pragma unroll
        for (int u = 0; u < QG; u++) {
            const float s = (j > pos_s[u]) ? -INFINITY : dot[u] * scale;
            sc[u][j] = s;
            lmax[u] = fmaxf(lmax[u], s);
        }
    }
#pragma unroll
    for (int u = 0; u < QG; u++) {
        float m = lmax[u];
#pragma unroll
        for (int o = 16; o > 0; o >>= 1) m = fmaxf(m, __shfl_xor_sync(0xffffffffu, m, o));
        if (lane == 0) red[u * 8 + wid] = m;
    }
    __syncthreads();
    float mx[QG];
#pragma unroll
    for (int u = 0; u < QG; u++) {
        float m = -INFINITY;
#pragma unroll
        for (int w = 0; w < 8; w++) m = fmaxf(m, red[u * 8 + w]);
        mx[u] = m;
    }
    __syncthreads();

    float lsum[QG];
#pragma unroll
    for (int u = 0; u < QG; u++) lsum[u] = 0.f;
    for (int j = t; j < LL; j += 256) {
#pragma unroll
        for (int u = 0; u < QG; u++) {
            const float p = __expf(sc[u][j] - mx[u]);
            sc[u][j] = p;
            lsum[u] += p;
        }
    }
#pragma unroll
    for (int u = 0; u < QG; u++) {
        float s = lsum[u];
#pragma unroll
        for (int o = 16; o > 0; o >>= 1) s += __shfl_xor_sync(0xffffffffu, s, o);
        if (lane == 0) red[u * 8 + wid] = s;
    }
    __syncthreads();
    float inv[QG];
#pragma unroll
    for (int u = 0; u < QG; u++) {
        float s = 0.f;
#pragma unroll
        for (int w = 0; w < 8; w++) s += red[u * 8 + w];
        inv[u] = 1.0f / s;
    }
    __syncthreads();

    const int d = t & 63, g4 = t >> 6;
    float acc[QG];
#pragma unroll
    for (int u = 0; u < QG; u++) acc[u] = 0.f;
    const int j0 = g4 * (LL / 4), j1 = j0 + (LL / 4);
    for (int j = j0; j < j1; j++) {
        const float v = vb[(size_t)j * DKK + d];
#pragma unroll
        for (int u = 0; u < QG; u++) acc[u] += sc[u][j] * v;
    }
#pragma unroll
    for (int u = 0; u < QG; u++) {
        red[t] = acc[u];
        __syncthreads();
        if (t < DKK) {
            const float o = (red[t] + red[t + 64] + red[t + 128] + red[t + 192]) * inv[u];
            g_att[(size_t)(bh * UU + grp * QG + u) * DKK + t] = o;
        }
        __syncthreads();
    }
}

// ---- cumsum, 3-phase ------------------------------------------------------
__global__ __launch_bounds__(256) void cumsum_p1()
{
    const int bh = blockIdx.x, ch = blockIdx.y;
    const int t = threadIdx.x;
    const int d = t & 63, seg = t >> 6;
    const float* vb = g_v + (size_t)bh * LL * DKK;
    const int l0 = ch * 128 + seg * 32;
    float s = 0.f;
#pragma unroll 4
    for (int l = l0; l < l0 + 32; l++) s += vb[(size_t)l * DKK + d];
    g_segsum[bh][ch][seg][d] = s;
}
__global__ __launch_bounds__(64) void cumsum_p2()
{
    const int bh = blockIdx.x, d = threadIdx.x;
    float run = 0.f;
#pragma unroll
    for (int ch = 0; ch < 16; ch++) {
        g_chpre[bh][ch][d] = run;
        run += g_segsum[bh][ch][0][d] + g_segsum[bh][ch][1][d] +
               g_segsum[bh][ch][2][d] + g_segsum[bh][ch][3][d];
    }
}
__global__ __launch_bounds__(256) void cumsum_p3()
{
    const int bh = blockIdx.x, ch = blockIdx.y;
    const int b = bh >> 3, h = bh & 7;
    const int t = threadIdx.x;
    const int d = t & 63, seg = t >> 6;
    const float* vb = g_v + (size_t)bh * LL * DKK;

    float off = g_chpre[bh][ch][d];
    for (int s = 0; s < seg; s++) off += g_segsum[bh][ch][s][d];

    const int l0 = ch * 128 + seg * 32;
    float acc = off;
    float* cb = g_ctx + (size_t)b * LL * DD + h * DKK;
#pragma unroll 4
    for (int l = l0; l < l0 + 32; l++) {
        acc += vb[(size_t)l * DKK + d];
        cb[(size_t)l * DD + d] = acc;
    }
}

__global__ void scatter_kernel()
{
    const int i = blockIdx.x * blockDim.x + threadIdx.x;
    if (i >= BB * HH * UU * DKK) return;
    const int d = i & 63;
    const int r = i >> 6;
    const int bh = r / UU;
    const int b = bh >> 3, h = bh & 7;
    const int pos = g_top[r];
    g_ctx[((size_t)b * LL + pos) * DD + h * DKK + d] = g_att[i];
}

// ---------------------------------------------------------------------------
extern "C" void kernel_launch(void* const* d_in, const int* in_sizes, int n_in,
                              void* d_out, int out_size)
{
    const float* queries = (const float*)d_in[0];
    const float* keys    = (const float*)d_in[1];
    const float* values  = (const float*)d_in[2];
    const int*   index_sample = (const int*)d_in[3];
    const float* Wq = (const float*)d_in[4];
    const float* bq = (const float*)d_in[5];
    const float* Wk = (const float*)d_in[6];
    const float* bk = (const float*)d_in[7];
    const float* Wv = (const float*)d_in[8];
    const float* bv = (const float*)d_in[9];
    const float* Wo = (const float*)d_in[10];
    const float* bo = (const float*)d_in[11];
    float* out = (float*)d_out;

    cudaFuncSetAttribute(hgemm_qkv, cudaFuncAttributeMaxDynamicSharedMemorySize, GSMEM);
    cudaFuncSetAttribute(hgemm_out, cudaFuncAttributeMaxDynamicSharedMemorySize, GSMEM);

    transpose_split_kernel<<<dim3(16, 16, 4), dim3(32, 8)>>>(Wq, Wk, Wv, Wo);

    hgemm_qkv<<<dim3(DD / 128, MTOT / 128, 3), 256, GSMEM>>>(queries, keys, values,
                                                             bq, bk, bv);

    probe_kernel<<<(BB * HH * LL * 32) / 256, 256>>>(index_sample);
    topk_kernel<<<BH, 256>>>();
    attn_kernel<<<BH * (UU / QG), 256>>>();
    cumsum_p1<<<dim3(BH, 16), 256>>>();
    cumsum_p2<<<BH, 64>>>();
    cumsum_p3<<<dim3(BH, 16), 256>>>();
    scatter_kernel<<<(BB * HH * UU * DKK + 255) / 256, 256>>>();

    hgemm_out<<<dim3(DD / 128, MTOT / 128, 1), 256, GSMEM>>>(bo, out);
}